// round 17
// baseline (speedup 1.0000x reference)
#include <cuda_runtime.h>
#include <math.h>
#include <float.h>

#define KF 32768
#define KI 16384
#define BB 16
#define HH 32
#define NROW (BB*HH)           // 512
#define SEGC 8                 // score partials per row (one per row-eighth)
#define GRID 592               // 148 SM * 4 blocks, all co-resident
#define GAMMA_C 0.3f
#define EPS_C 1e-6f
#define L2E 1.4426950408889634f

// ---- scratch (static device arrays; no allocations) ----
__device__ float  g_RI[BB * KF * 2];      // interleaved (rf, indicator)
__device__ float  g_pstat[256 * 2];       // partial (sum,sumsq) per (b,f,quarter)
__device__ int    g_ccnt[BB * 16];        // mask ones per 2048-chunk
__device__ float4 g_part[NROW * SEGC];    // per (row,eighth): zi,p,sm,0
__device__ float  g_ca[NROW], g_cb[NROW];
__device__ unsigned g_cnt;                // barrier arrivals
__device__ volatile unsigned g_sense;     // barrier sense (monotonic)

__device__ __forceinline__ float fast_ex2(float x) {
    float y;
    asm("ex2.approx.ftz.f32 %0, %1;" : "=f"(y) : "f"(x));
    return y;
}

struct F8 { float v[8]; };
__device__ __forceinline__ F8 ldg256_el(const float* p) {
    unsigned r0,r1,r2,r3,r4,r5,r6,r7;
    asm volatile("ld.global.L2::evict_last.v8.b32 {%0,%1,%2,%3,%4,%5,%6,%7}, [%8];"
                 : "=r"(r0),"=r"(r1),"=r"(r2),"=r"(r3),
                   "=r"(r4),"=r"(r5),"=r"(r6),"=r"(r7) : "l"(p));
    F8 o;
    o.v[0]=__uint_as_float(r0); o.v[1]=__uint_as_float(r1);
    o.v[2]=__uint_as_float(r2); o.v[3]=__uint_as_float(r3);
    o.v[4]=__uint_as_float(r4); o.v[5]=__uint_as_float(r5);
    o.v[6]=__uint_as_float(r6); o.v[7]=__uint_as_float(r7);
    return o;
}

// grid barrier: all GRID blocks co-resident (enforced by __launch_bounds__)
__device__ __forceinline__ void gsync(unsigned& ls) {
    __threadfence();
    __syncthreads();
    if (threadIdx.x == 0) {
        ls++;
        if (atomicAdd(&g_cnt, 1u) == GRID - 1) {
            atomicExch(&g_cnt, 0u);
            __threadfence();
            g_sense = ls;       // release
        } else {
            while (g_sense != ls) __nanosleep(64);
            __threadfence();
        }
    }
    __syncthreads();
}

__global__ void __launch_bounds__(256, 4) fused_kernel(
    const float* __restrict__ attn, const int* __restrict__ mask,
    const float* __restrict__ fC, const float* __restrict__ fA,
    const float* __restrict__ fD, const float* __restrict__ fB,
    float* __restrict__ out)
{
    const int bx = blockIdx.x;
    const int tid = threadIdx.x;
    const int lane = tid & 31, warp = tid >> 5;
    unsigned ls = g_sense;   // stable at kernel start (before any release)

    __shared__ float s_r1[8], s_r2[8];
    __shared__ int   s_wsum[8];

    const float* fptr[4] = {fC, fA, fD, fB};

    // ========= Phase A: stats partials (blocks 0-255) + mask chunk counts (256-511) =========
    if (bx < 256) {
        const int bf = bx >> 2, quarter = bx & 3;
        const int b = bf >> 2, f = bf & 3;
        const float4* P = (const float4*)(fptr[f] + b * KI + quarter * 4096);
        float s = 0.f, s2 = 0.f;
#pragma unroll
        for (int k = 0; k < 4; k++) {
            float4 v = P[tid + k * 256];
            s  += (v.x + v.y) + (v.z + v.w);
            s2 += (v.x*v.x + v.y*v.y) + (v.z*v.z + v.w*v.w);
        }
#pragma unroll
        for (int off = 16; off; off >>= 1) {
            s  += __shfl_down_sync(0xffffffffu, s,  off);
            s2 += __shfl_down_sync(0xffffffffu, s2, off);
        }
        if (lane == 0) { s_r1[warp] = s; s_r2[warp] = s2; }
        __syncthreads();
        if (tid == 0) {
            s = 0.f; s2 = 0.f;
#pragma unroll
            for (int w = 0; w < 8; w++) { s += s_r1[w]; s2 += s_r2[w]; }
            g_pstat[bx*2]   = s;
            g_pstat[bx*2+1] = s2;
        }
    } else if (bx < 512) {
        const int cu = bx - 256;         // b*16 + chunk
        const int b = cu >> 4, chunk = cu & 15;
        const int4* M = (const int4*)(mask + b * KF + chunk * 2048);
        int cnt = 0;
#pragma unroll
        for (int k = 0; k < 2; k++) {
            int4 m = M[tid + k * 256];
            cnt += m.x + m.y + m.z + m.w;
        }
#pragma unroll
        for (int off = 16; off; off >>= 1)
            cnt += __shfl_down_sync(0xffffffffu, cnt, off);
        if (lane == 0) s_wsum[warp] = cnt;
        __syncthreads();
        if (tid == 0) {
            cnt = 0;
#pragma unroll
            for (int w = 0; w < 8; w++) cnt += s_wsum[w];
            g_ccnt[cu] = cnt;
        }
    }
    gsync(ls);

    // ========= Phase B: pack (rf, indicator). 256 blocks, chunk=2048 positions =========
    if (bx < 256) {
        const int b = bx >> 4, chunk = bx & 15;
        const int P0 = chunk * 2048;

        // redundant per-block stats finalize (32 tiny L2 reads)
        float mu[4], ivs[4];
#pragma unroll
        for (int f = 0; f < 4; f++) {
            float s = 0.f, s2 = 0.f;
#pragma unroll
            for (int q = 0; q < 4; q++) {
                s  += g_pstat[((b*4+f)*4 + q)*2];
                s2 += g_pstat[((b*4+f)*4 + q)*2 + 1];
            }
            float m = s * (1.f / KI);
            float var = s2 * (1.f / KI) - m * m;
            mu[f]  = m;
            ivs[f] = 1.f / (sqrtf(fmaxf(var, 0.f)) + EPS_C);
        }
        // redundant chunk-rank base
        int cbase = 0;
        for (int c = 0; c < chunk; c++) cbase += g_ccnt[b*16 + c];

        const float* pC = fC + b*KI;
        const float* pA = fA + b*KI;
        const float* pD = fD + b*KI;
        const float* pB = fB + b*KI;

        int mbits[8];
        int cnt = 0;
        {
            const int4* M = (const int4*)(mask + b * KF + P0 + tid * 8);
            int4 m0 = M[0], m1 = M[1];
            mbits[0]=m0.x; mbits[1]=m0.y; mbits[2]=m0.z; mbits[3]=m0.w;
            mbits[4]=m1.x; mbits[5]=m1.y; mbits[6]=m1.z; mbits[7]=m1.w;
            cnt = m0.x+m0.y+m0.z+m0.w + m1.x+m1.y+m1.z+m1.w;
        }
        int inc = cnt;
#pragma unroll
        for (int off = 1; off < 32; off <<= 1) {
            int v = __shfl_up_sync(0xffffffffu, inc, off);
            if (lane >= off) inc += v;
        }
        if (lane == 31) s_wsum[warp] = inc;
        __syncthreads();
        int wbase = 0;
#pragma unroll
        for (int w = 0; w < 8; w++) {
            int v = s_wsum[w];
            if (w < warp) wbase += v;
        }
        int r = cbase + wbase + inc - cnt;   // rank of this thread's first image pos

        float4 riv[4];
#pragma unroll
        for (int i = 0; i < 8; i++) {
            float rv, ivv;
            if (mbits[i]) {
                float zc = (pC[r] - mu[0]) * ivs[0];
                float za = (pA[r] - mu[1]) * ivs[1];
                float zd = (pD[r] - mu[2]) * ivs[2];
                float zb = (pB[r] - mu[3]) * ivs[3];
                float Ct = fmaxf(zc, 0.f);
                float At = 1.f / (1.f + fast_ex2(-za * L2E));
                float Dt = 1.f / (1.f + fast_ex2(-zd * L2E));
                float Bt = 1.f / (1.f + fast_ex2(-zb * L2E));
                float denom = fmaxf(1.f + 0.5f * (Dt + Bt), EPS_C);
                rv = Ct * At / denom;
                ivv = 1.f;
                r++;
            } else { rv = 0.f; ivv = 0.f; }
            if (i & 1) { riv[i>>1].z = rv; riv[i>>1].w = ivv; }
            else       { riv[i>>1].x = rv; riv[i>>1].y = ivv; }
        }
        float4* RIp = (float4*)(g_RI + (size_t)(b * KF + P0 + tid * 8) * 2);
#pragma unroll
        for (int i = 0; i < 4; i++) RIp[i] = riv[i];
    }
    gsync(ls);

    // ========= Phase C: score — one warp per row-eighth (4096 floats), ONE reduction =========
    {
        const int wgid = bx * 8 + warp;
        if (wgid < NROW * SEGC) {            // 4096 warp-units, single wave
            const int row = wgid >> 3;
            const int eighth = wgid & 7;
            const int b = row >> 5;
            const float* A = attn + (size_t)row * KF + (size_t)eighth * 4096;
            const float4* RIq = (const float4*)(g_RI + (size_t)b * KF * 2)
                                + (size_t)eighth * 2048;

            float zi = 0.f, p = 0.f, sm = 0.f;
#pragma unroll
            for (int it = 0; it < 8; it++) {
                const int i8 = it * 64 + lane;          // f8 index within eighth
                F8 x0 = ldg256_el(A + (size_t)i8 * 8);          // front-batched pair
                F8 x1 = ldg256_el(A + (size_t)(i8 + 32) * 8);
                const float4* ri0 = RIq + (size_t)i8 * 4;
                const float4* ri1 = ri0 + 128;
#pragma unroll
                for (int c = 0; c < 4; c++) {
                    float4 w4 = __ldg(ri0 + c);
                    float e0 = fast_ex2(x0.v[2*c]   * L2E);
                    float e1 = fast_ex2(x0.v[2*c+1] * L2E);
                    zi = fmaf(e0, w4.y, fmaf(e1, w4.w, zi));
                    p  = fmaf(e0, w4.x, fmaf(e1, w4.z, p));
                    sm = fmaf(e0, fminf(w4.x, 1.f), fmaf(e1, fminf(w4.z, 1.f), sm));
                }
#pragma unroll
                for (int c = 0; c < 4; c++) {
                    float4 w4 = __ldg(ri1 + c);
                    float e0 = fast_ex2(x1.v[2*c]   * L2E);
                    float e1 = fast_ex2(x1.v[2*c+1] * L2E);
                    zi = fmaf(e0, w4.y, fmaf(e1, w4.w, zi));
                    p  = fmaf(e0, w4.x, fmaf(e1, w4.z, p));
                    sm = fmaf(e0, fminf(w4.x, 1.f), fmaf(e1, fminf(w4.z, 1.f), sm));
                }
            }
#pragma unroll
            for (int off = 16; off; off >>= 1) {
                zi += __shfl_down_sync(0xffffffffu, zi, off);
                p  += __shfl_down_sync(0xffffffffu, p,  off);
                sm += __shfl_down_sync(0xffffffffu, sm, off);
            }
            if (lane == 0)
                g_part[row * SEGC + eighth] = make_float4(zi, p, sm, 0.f);
        }
    }
    gsync(ls);

    // ========= Phase D: finalize + top-7 select (2 blocks, warp per batch) =========
    if (bx < 2) {
        const int b = bx * 8 + warp;
        const int row = b * HH + lane;
        float zi = 0.f, p = 0.f, sm = 0.f;
#pragma unroll
        for (int k = 0; k < SEGC; k++) {
            float4 v = g_part[row * SEGC + k];
            zi += v.x; p += v.y; sm += v.z;
        }
        const float sp = p / zi;
        const float sn = (zi - sm) / zi;

        bool sel = false;
#pragma unroll
        for (int t = 0; t < 7; t++) {
            float cv = sel ? -FLT_MAX : sp;
            int ci = lane;
#pragma unroll
            for (int off = 16; off; off >>= 1) {
                float ov = __shfl_down_sync(0xffffffffu, cv, off);
                int   oi = __shfl_down_sync(0xffffffffu, ci, off);
                if (ov > cv || (ov == cv && oi < ci)) { cv = ov; ci = oi; }
            }
            int win = __shfl_sync(0xffffffffu, ci, 0);
            if (lane == win) sel = true;
        }
        const bool mpos = sel && (sp > 0.f);

        const float ns = mpos ? -FLT_MAX : sn;
        sel = false;
#pragma unroll
        for (int t = 0; t < 7; t++) {
            float cv = sel ? -FLT_MAX : ns;
            int ci = lane;
#pragma unroll
            for (int off = 16; off; off >>= 1) {
                float ov = __shfl_down_sync(0xffffffffu, cv, off);
                int   oi = __shfl_down_sync(0xffffffffu, ci, off);
                if (ov > cv || (ov == cv && oi < ci)) { cv = ov; ci = oi; }
            }
            int win = __shfl_sync(0xffffffffu, ci, 0);
            if (lane == win) sel = true;
        }
        const bool mneg = sel && (ns > 0.f);

        g_ca[row] = mpos ? GAMMA_C : 0.f;
        g_cb[row] = mneg ? GAMMA_C : 0.f;
    }
    gsync(ls);

    // ========= Phase E: apply (attn L2-warm), 4-way strided for MLP =========
    {
        const float4* Ap = (const float4*)attn;
        float4* Op = (float4*)out;
        const int NF4 = NROW * (KF / 4);          // 4,194,304
        const int stride = GRID * 256;

        for (int i0 = bx * 256 + tid; i0 < NF4; i0 += 4 * stride) {
            int idx[4];
            float4 x[4];
            int nv = 0;
#pragma unroll
            for (int k = 0; k < 4; k++) {
                int i = i0 + k * stride;
                if (i < NF4) { idx[nv] = i; x[nv] = __ldcs(&Ap[i]); nv++; }
            }
#pragma unroll 4
            for (int k = 0; k < nv; k++) {
                const int i = idx[k];
                const int bh = i >> 13;
                const float a = __ldg(&g_ca[bh]);
                const float c = __ldg(&g_cb[bh]);
                float4 xx = x[k];
                if (a == 0.f && c == 0.f) {
                    __stcs(&Op[i], xx);
                } else {
                    const int b = bh >> 5;
                    const int posf4 = i & 8191;
                    const float4* RIf4 = (const float4*)(g_RI + (size_t)b * KF * 2);
                    float4 r0 = RIf4[2*posf4];
                    float4 r1 = RIf4[2*posf4 + 1];
                    float4 o;
                    float R, I, w;
                    R = r0.x; I = r0.y; w = fmaxf(1.f - R, 0.f) * I;
                    o.x = fmaf(a, R, fmaf(-c, w, xx.x));
                    R = r0.z; I = r0.w; w = fmaxf(1.f - R, 0.f) * I;
                    o.y = fmaf(a, R, fmaf(-c, w, xx.y));
                    R = r1.x; I = r1.y; w = fmaxf(1.f - R, 0.f) * I;
                    o.z = fmaf(a, R, fmaf(-c, w, xx.z));
                    R = r1.z; I = r1.w; w = fmaxf(1.f - R, 0.f) * I;
                    o.w = fmaf(a, R, fmaf(-c, w, xx.w));
                    __stcs(&Op[i], o);
                }
            }
        }
    }
}

// ============================================================
extern "C" void kernel_launch(void* const* d_in, const int* in_sizes, int n_in,
                              void* d_out, int out_size)
{
    const float* attn = (const float*)d_in[0];
    const int*   mask = (const int*)  d_in[1];
    const float* fC   = (const float*)d_in[2];
    const float* fA   = (const float*)d_in[3];
    const float* fD   = (const float*)d_in[4];
    const float* fB   = (const float*)d_in[5];
    float* out = (float*)d_out;

    fused_kernel<<<GRID, 256>>>(attn, mask, fC, fA, fD, fB, out);
}